// round 4
// baseline (speedup 1.0000x reference)
#include <cuda_runtime.h>
#include <math.h>
#include <float.h>

#define NB 4
#define NP 4096
#define NC 256
#define NK 16
#define NPTS (NB*NP)      /* 16384 */
#define NROWS (NPTS*NK)   /* 262144 */

// ---------------- scratch (device globals; no allocation) ----------------
__device__ float g_q [NPTS*NC];
__device__ float g_kf[NPTS*NC];
__device__ float g_vf[NPTS*NC];
__device__ int   g_idx[NROWS];
__device__ float g_u [NROWS*3];
__device__ float g_h [NROWS*NC];   // h, later reused for attn
__device__ float g_h2[NROWS*NC];
__device__ float g_bnd[6];         // scale[3], shift[3] for d-path BN
__device__ float g_partd[512*6];
__device__ float g_ps1[512*NC];
__device__ float g_pq1[512*NC];
__device__ float g_ps2[2048*NC];
__device__ float g_pq2[2048*NC];
__device__ float g_bn1[2*NC];
__device__ float g_bn2[2*NC];

// Bit-exact replication of the reference's fp32 rounding:
//   sq  = ((x*x + y*y) + z*z)            -- separate mul + sequential reduce
//   dot = fma(z,z', fma(y,y', x*x'))     -- K=3 gemm fma accumulation chain
//   d   = (sq_n + sq_m) - (2*dot)        -- elementwise, each op rounded
__device__ __forceinline__ float sq3_exact(float x, float y, float z){
    return __fadd_rn(__fadd_rn(__fmul_rn(x,x), __fmul_rn(y,y)), __fmul_rn(z,z));
}
__device__ __forceinline__ float dist_exact(float qx,float qy,float qz,float qw,
                                            float px,float py,float pz,float pw){
    float dot = __fmaf_rn(qz, pz, __fmaf_rn(qy, py, __fmul_rn(qx, px)));
    return __fsub_rn(__fadd_rn(qw, pw), __fmul_rn(2.0f, dot));
}

// ---------------- KNN: one warp per query, chunked smem points ----------------
__global__ __launch_bounds__(512) void knn_kernel(const float* __restrict__ xyz)
{
    constexpr int CH = 2048;
    __shared__ float4 pts[CH];
    int b = blockIdx.y;
    const float* xb = xyz + b*NP*3;
    int warp = threadIdx.x >> 5, lane = threadIdx.x & 31;
    int n = blockIdx.x*16 + warp;
    float qx = xb[n*3+0], qy = xb[n*3+1], qz = xb[n*3+2];
    float qw = sq3_exact(qx, qy, qz);
    float dl[NK]; int il[NK];
#pragma unroll
    for (int j=0;j<NK;j++){ dl[j]=FLT_MAX; il[j]=0x7fffffff; }

    for (int c0=0;c0<NP;c0+=CH){
        __syncthreads();
        for (int i=threadIdx.x;i<CH;i+=512){
            int m=c0+i;
            float x=xb[m*3],y=xb[m*3+1],z=xb[m*3+2];
            pts[i]=make_float4(x,y,z, sq3_exact(x,y,z));
        }
        __syncthreads();
        for (int i=lane;i<CH;i+=32){
            float4 p=pts[i];
            int m=c0+i;
            float d = dist_exact(qx,qy,qz,qw, p.x,p.y,p.z,p.w);
            if (d < dl[NK-1] || (d==dl[NK-1] && m<il[NK-1])){
                dl[NK-1]=d; il[NK-1]=m;
#pragma unroll
                for (int j=NK-1;j>0;j--){
                    bool sw = dl[j]<dl[j-1] || (dl[j]==dl[j-1] && il[j]<il[j-1]);
                    float t0 = sw? dl[j-1]:dl[j];
                    float t1 = sw? dl[j]:dl[j-1];
                    int   i0 = sw? il[j-1]:il[j];
                    int   i1 = sw? il[j]:il[j-1];
                    dl[j]=t0; dl[j-1]=t1; il[j]=i0; il[j-1]=i1;
                }
            }
        }
    }
    // warp-wide merge of 32 sorted lists -> global top-16
    for (int r=0;r<NK;r++){
        float cd = dl[0]; int ci = il[0];
        float rd = cd;    int ri = ci;
#pragma unroll
        for (int off=16; off>0; off>>=1){
            float od = __shfl_down_sync(0xffffffffu, rd, off);
            int   oi = __shfl_down_sync(0xffffffffu, ri, off);
            if (od<rd || (od==rd && oi<ri)){ rd=od; ri=oi; }
        }
        rd = __shfl_sync(0xffffffffu, rd, 0);
        ri = __shfl_sync(0xffffffffu, ri, 0);
        if (lane==0) g_idx[(b*NP+n)*NK + r] = ri;
        if (cd==rd && ci==ri){
#pragma unroll
            for (int j=0;j<NK-1;j++){ dl[j]=dl[j+1]; il[j]=il[j+1]; }
            dl[NK-1]=FLT_MAX; il[NK-1]=0x7fffffff;
        }
    }
}

// ---------------- d-path BN stats: t = rel@d1_w + d1_b, 3 channels ----------------
__global__ __launch_bounds__(256) void dstat_kernel(const float* __restrict__ xyz,
                                                    const float* __restrict__ d1w,
                                                    const float* __restrict__ d1b)
{
    float s[3]={0.f,0.f,0.f}, sq[3]={0.f,0.f,0.f};
    int stride = gridDim.x*blockDim.x;
    for (int it = blockIdx.x*blockDim.x+threadIdx.x; it < NROWS; it += stride){
        int pt = it >> 4;
        int b  = pt >> 12;
        int j  = g_idx[it];
        float r0 = xyz[pt*3+0] - xyz[(b*NP+j)*3+0];
        float r1 = xyz[pt*3+1] - xyz[(b*NP+j)*3+1];
        float r2 = xyz[pt*3+2] - xyz[(b*NP+j)*3+2];
#pragma unroll
        for (int d=0;d<3;d++){
            float t = r0*d1w[d] + r1*d1w[3+d] + r2*d1w[6+d] + d1b[d];
            s[d]+=t; sq[d]+=t*t;
        }
    }
    __shared__ float red[256];
    for (int q=0;q<6;q++){
        red[threadIdx.x] = (q<3)? s[q] : sq[q-3];
        __syncthreads();
        for (int st=128; st; st>>=1){
            if (threadIdx.x<st) red[threadIdx.x]+=red[threadIdx.x+st];
            __syncthreads();
        }
        if (threadIdx.x==0) g_partd[blockIdx.x*6+q]=red[0];
        __syncthreads();
    }
}

__global__ void dfin_kernel(const float* __restrict__ g, const float* __restrict__ beta)
{
    int d = threadIdx.x;
    if (d>=3) return;
    double s=0.0,q=0.0;
    for (int i=0;i<512;i++){ s+=g_partd[i*6+d]; q+=g_partd[i*6+3+d]; }
    double m = s/(double)NROWS;
    double v = q/(double)NROWS - m*m;
    double sc = (double)g[d] / sqrt(v+1e-5);
    g_bnd[d]   = (float)sc;
    g_bnd[3+d] = (float)((double)beta[d] - m*sc);
}

// ---------------- generic fp32 GEMM: C[MxN] = f(A)[Mx256] @ B[256xN] + bias ----------------
// Double-buffered register-staged K-pipeline: LDG for tile t+1 issued before the
// FFMA block of tile t (so the ~600cyc DRAM latency hides under ~2000 issue slots),
// then transform+STS into the alternate smem stage.
// BNRELU: A element -> max(0, a*bnp[c]+bnp[256+c]).  STATS: per-column sum/sumsq partials.
template<bool BNRELU, bool STATS>
__global__ __launch_bounds__(256, 2) void gemm_kernel(
    const float* __restrict__ A, const float* __restrict__ Bm,
    const float* __restrict__ bias, float* __restrict__ C,
    const float* __restrict__ bnp, float* __restrict__ psum, float* __restrict__ psq)
{
    __shared__ __align__(16) float As[2][8][132];
    __shared__ __align__(16) float Bs[2][8][132];
    __shared__ float red[16][128];
    int tid = threadIdx.x;
    int tx = tid & 15, ty = tid >> 4;
    int mblk = blockIdx.x, nblk = blockIdx.y;
    int arow = tid >> 1, acg = (tid & 1)*4;
    int brow = tid >> 5, bcol = (tid & 31)*4;
    const float* Aptr = A + (size_t)(mblk*128 + arow)*256;
    const float* Bptr = Bm + nblk*128;
    float acc[8][8];
#pragma unroll
    for (int i=0;i<8;i++)
#pragma unroll
        for (int j=0;j<8;j++) acc[i][j]=0.f;

    // ---- prologue: stage tile 0 ----
    {
        float4 av = *(const float4*)(Aptr + acg);
        if (BNRELU){
            int c = acg;
            av.x = fmaxf(0.f, fmaf(av.x, bnp[c+0], bnp[256+c+0]));
            av.y = fmaxf(0.f, fmaf(av.y, bnp[c+1], bnp[256+c+1]));
            av.z = fmaxf(0.f, fmaf(av.z, bnp[c+2], bnp[256+c+2]));
            av.w = fmaxf(0.f, fmaf(av.w, bnp[c+3], bnp[256+c+3]));
        }
        As[0][acg+0][arow]=av.x; As[0][acg+1][arow]=av.y;
        As[0][acg+2][arow]=av.z; As[0][acg+3][arow]=av.w;
        float4 bv = *(const float4*)(Bptr + brow*256 + bcol);
        *(float4*)&Bs[0][brow][bcol] = bv;
    }
    __syncthreads();

    int buf = 0;
#pragma unroll 2
    for (int k0=0; k0<256; k0+=8){
        // issue next tile's global loads BEFORE the FFMA block
        float4 av2, bv2;
        bool has_next = (k0+8 < 256);
        if (has_next){
            av2 = *(const float4*)(Aptr + (k0+8) + acg);
            bv2 = *(const float4*)(Bptr + (k0+8+brow)*256 + bcol);
        }
        // compute on current stage
#pragma unroll
        for (int kk=0;kk<8;kk++){
            float a[8], bb[8];
            *(float4*)(a)    = *(const float4*)&As[buf][kk][ty*8];
            *(float4*)(a+4)  = *(const float4*)&As[buf][kk][ty*8+4];
            *(float4*)(bb)   = *(const float4*)&Bs[buf][kk][tx*8];
            *(float4*)(bb+4) = *(const float4*)&Bs[buf][kk][tx*8+4];
#pragma unroll
            for (int i=0;i<8;i++)
#pragma unroll
                for (int j=0;j<8;j++) acc[i][j] = fmaf(a[i], bb[j], acc[i][j]);
        }
        // stage next tile into the alternate buffer
        if (has_next){
            if (BNRELU){
                int c = k0+8+acg;
                av2.x = fmaxf(0.f, fmaf(av2.x, bnp[c+0], bnp[256+c+0]));
                av2.y = fmaxf(0.f, fmaf(av2.y, bnp[c+1], bnp[256+c+1]));
                av2.z = fmaxf(0.f, fmaf(av2.z, bnp[c+2], bnp[256+c+2]));
                av2.w = fmaxf(0.f, fmaf(av2.w, bnp[c+3], bnp[256+c+3]));
            }
            int nb = buf^1;
            As[nb][acg+0][arow]=av2.x; As[nb][acg+1][arow]=av2.y;
            As[nb][acg+2][arow]=av2.z; As[nb][acg+3][arow]=av2.w;
            *(float4*)&Bs[nb][brow][bcol] = bv2;
            __syncthreads();
            buf = nb;
        }
    }

    float bvr[8];
#pragma unroll
    for (int j=0;j<8;j++) bvr[j] = bias[nblk*128 + tx*8 + j];
    float cs[8], cq[8];
#pragma unroll
    for (int j=0;j<8;j++){ cs[j]=0.f; cq[j]=0.f; }
#pragma unroll
    for (int i=0;i<8;i++){
        int row = mblk*128 + ty*8 + i;
        float o[8];
#pragma unroll
        for (int j=0;j<8;j++){
            float v = acc[i][j] + bvr[j];
            o[j]=v;
            if (STATS){ cs[j]+=v; cq[j]+=v*v; }
        }
        float* cp = C + (size_t)row*256 + nblk*128 + tx*8;
        *(float4*)cp     = make_float4(o[0],o[1],o[2],o[3]);
        *(float4*)(cp+4) = make_float4(o[4],o[5],o[6],o[7]);
    }

    if (STATS){
        __syncthreads();
#pragma unroll
        for (int j=0;j<8;j++) red[ty][tx*8+j]=cs[j];
        __syncthreads();
        for (int st=8; st>0; st>>=1){
            if (ty<st){
#pragma unroll
                for (int j=0;j<8;j++) red[ty][tx*8+j]+=red[ty+st][tx*8+j];
            }
            __syncthreads();
        }
        if (ty==0){
#pragma unroll
            for (int j=0;j<8;j++) psum[mblk*256 + nblk*128 + tx*8 + j] = red[0][tx*8+j];
        }
        __syncthreads();
#pragma unroll
        for (int j=0;j<8;j++) red[ty][tx*8+j]=cq[j];
        __syncthreads();
        for (int st=8; st>0; st>>=1){
            if (ty<st){
#pragma unroll
                for (int j=0;j<8;j++) red[ty][tx*8+j]+=red[ty+st][tx*8+j];
            }
            __syncthreads();
        }
        if (ty==0){
#pragma unroll
            for (int j=0;j<8;j++) psq[mblk*256 + nblk*128 + tx*8 + j] = red[0][tx*8+j];
        }
    }
}

// ---------------- finalize per-channel BN over 256 channels ----------------
__global__ __launch_bounds__(256) void bnfin_kernel(const float* __restrict__ psum,
                                                    const float* __restrict__ psq, int P,
                                                    const float* __restrict__ g,
                                                    const float* __restrict__ beta,
                                                    float* __restrict__ outp)
{
    int c = threadIdx.x;
    double s=0.0,q=0.0;
    for (int i=0;i<P;i++){ s+=psum[i*NC+c]; q+=psq[i*NC+c]; }
    double m = s/(double)NROWS;
    double v = q/(double)NROWS - m*m;
    double sc = (double)g[c] / sqrt(v+1e-5);
    outp[c]    = (float)sc;
    outp[NC+c] = (float)((double)beta[c] - m*sc);
}

// ---------------- h producer: h = q - k[idx] + pos_enc; fused channel stats ----------------
__global__ __launch_bounds__(256) void hprod_kernel(
    const float* __restrict__ xyz, const float* __restrict__ d1w, const float* __restrict__ d1b,
    const float* __restrict__ d2w, const float* __restrict__ d2b)
{
    __shared__ float su[NK*3];
    __shared__ int   sj[NK];
    int c = threadIdx.x;
    float d2c0 = d2w[c], d2c1 = d2w[256+c], d2c2 = d2w[512+c], d2bc = d2b[c];
    float s=0.f, q=0.f;
    for (int pp=0; pp<32; pp++){
        int pt = blockIdx.x*32 + pp;
        int b  = pt >> 12;
        if (c < NK){
            int k = c;
            int j = g_idx[pt*NK+k];
            sj[k]=j;
            float r0 = xyz[pt*3+0]-xyz[(b*NP+j)*3+0];
            float r1 = xyz[pt*3+1]-xyz[(b*NP+j)*3+1];
            float r2 = xyz[pt*3+2]-xyz[(b*NP+j)*3+2];
#pragma unroll
            for (int d=0;d<3;d++){
                float t  = r0*d1w[d] + r1*d1w[3+d] + r2*d1w[6+d] + d1b[d];
                float uu = fmaxf(0.f, fmaf(t, g_bnd[d], g_bnd[3+d]));
                su[k*3+d]=uu;
                g_u[(pt*NK+k)*3+d]=uu;
            }
        }
        __syncthreads();
        float qv = g_q[pt*NC + c];
#pragma unroll
        for (int k=0;k<NK;k++){
            int j = sj[k];
            float kv = g_kf[(b*NP+j)*NC + c];
            float pe = su[k*3]*d2c0 + su[k*3+1]*d2c1 + su[k*3+2]*d2c2 + d2bc;
            float h = qv - kv + pe;
            g_h[(size_t)(pt*NK+k)*NC + c] = h;
            s += h; q += h*h;
        }
        __syncthreads();
    }
    g_ps1[blockIdx.x*NC+c]=s;
    g_pq1[blockIdx.x*NC+c]=q;
}

// ---------------- softmax over K + weighted gather output ----------------
__global__ __launch_bounds__(256) void out_kernel(
    float* __restrict__ out, const float* __restrict__ d2w, const float* __restrict__ d2b)
{
    __shared__ float su[NK*3];
    __shared__ int   sj[NK];
    int pt = blockIdx.x;
    int b  = pt >> 12;
    int a  = threadIdx.x;
    if (a < NK)   sj[a] = g_idx[pt*NK+a];
    if (a < NK*3) su[a] = g_u[pt*NK*3 + a];
    __syncthreads();
    float d0=d2w[a], d1=d2w[256+a], d2=d2w[512+a], db=d2b[a];
    float e[NK];
    float mx = -FLT_MAX;
#pragma unroll
    for (int k=0;k<NK;k++){
        float x = g_h[(size_t)(pt*NK+k)*NC + a];   // attn logits (g_h reused)
        e[k]=x; mx = fmaxf(mx,x);
    }
    float sm=0.f;
#pragma unroll
    for (int k=0;k<NK;k++){ e[k]=expf(e[k]-mx); sm+=e[k]; }
    float inv = 1.f/sm;
    float o=0.f;
#pragma unroll
    for (int k=0;k<NK;k++){
        int j = sj[k];
        float v  = g_vf[(b*NP+j)*NC + a];
        float pe = su[k*3]*d0 + su[k*3+1]*d1 + su[k*3+2]*d2 + db;
        o += e[k]*inv*(v+pe);
    }
    out[pt*NC + a] = o;
}

// ---------------- host launcher (graph-capturable, allocation-free) ----------------
extern "C" void kernel_launch(void* const* d_in, const int* in_sizes, int n_in,
                              void* d_out, int out_size)
{
    const float* xyz  = (const float*)d_in[0];
    const float* feat = (const float*)d_in[1];
    const float* wq   = (const float*)d_in[2];  const float* bq  = (const float*)d_in[3];
    const float* wk   = (const float*)d_in[4];  const float* bk  = (const float*)d_in[5];
    const float* wv   = (const float*)d_in[6];  const float* bv  = (const float*)d_in[7];
    const float* d1w  = (const float*)d_in[8];  const float* d1b = (const float*)d_in[9];
    const float* bndg = (const float*)d_in[10]; const float* bndb= (const float*)d_in[11];
    const float* d2w  = (const float*)d_in[12]; const float* d2b = (const float*)d_in[13];
    const float* g1g  = (const float*)d_in[14]; const float* g1bt= (const float*)d_in[15];
    const float* g1w  = (const float*)d_in[16]; const float* g1b = (const float*)d_in[17];
    const float* g2g  = (const float*)d_in[18]; const float* g2bt= (const float*)d_in[19];
    const float* g2w  = (const float*)d_in[20]; const float* g2b = (const float*)d_in[21];
    float* out = (float*)d_out;

    float *p_q,*p_kf,*p_vf,*p_h,*p_h2,*p_bn1,*p_bn2,*p_ps1,*p_pq1,*p_ps2,*p_pq2;
    cudaGetSymbolAddress((void**)&p_q,  g_q);
    cudaGetSymbolAddress((void**)&p_kf, g_kf);
    cudaGetSymbolAddress((void**)&p_vf, g_vf);
    cudaGetSymbolAddress((void**)&p_h,  g_h);
    cudaGetSymbolAddress((void**)&p_h2, g_h2);
    cudaGetSymbolAddress((void**)&p_bn1,g_bn1);
    cudaGetSymbolAddress((void**)&p_bn2,g_bn2);
    cudaGetSymbolAddress((void**)&p_ps1,g_ps1);
    cudaGetSymbolAddress((void**)&p_pq1,g_pq1);
    cudaGetSymbolAddress((void**)&p_ps2,g_ps2);
    cudaGetSymbolAddress((void**)&p_pq2,g_pq2);

    // 1. KNN indices
    knn_kernel<<<dim3(NP/16, NB), 512>>>(xyz);
    // 2. d-path BN stats + finalize
    dstat_kernel<<<512,256>>>(xyz, d1w, d1b);
    dfin_kernel<<<1,32>>>(bndg, bndb);
    // 3. q / k / v projections
    gemm_kernel<false,false><<<dim3(NPTS/128,2),256>>>(feat, wq, bq, p_q,  nullptr, nullptr, nullptr);
    gemm_kernel<false,false><<<dim3(NPTS/128,2),256>>>(feat, wk, bk, p_kf, nullptr, nullptr, nullptr);
    gemm_kernel<false,false><<<dim3(NPTS/128,2),256>>>(feat, wv, bv, p_vf, nullptr, nullptr, nullptr);
    // 4. h = q - k[idx] + pos_enc (stores u, fused bn1 stats)
    hprod_kernel<<<512,256>>>(xyz, d1w, d1b, d2w, d2b);
    bnfin_kernel<<<1,256>>>(p_ps1, p_pq1, 512, g1g, g1bt, p_bn1);
    // 5. gamma layer 1: relu(bn1(h)) @ g1_w + g1_b  (fused bn2 stats)
    gemm_kernel<true,true><<<dim3(NROWS/128,2),256>>>(p_h, g1w, g1b, p_h2, p_bn1, p_ps2, p_pq2);
    bnfin_kernel<<<1,256>>>(p_ps2, p_pq2, 2048, g2g, g2bt, p_bn2);
    // 6. gamma layer 2: relu(bn2(h2)) @ g2_w + g2_b -> attn logits (into g_h)
    gemm_kernel<true,false><<<dim3(NROWS/128,2),256>>>(p_h2, g2w, g2b, p_h, p_bn2, nullptr, nullptr);
    // 7. softmax over K + weighted (v + pos_enc) sum
    out_kernel<<<NPTS,256>>>(out, d2w, d2b);
}

// round 7
// speedup vs baseline: 1.3110x; 1.3110x over previous
#include <cuda_runtime.h>
#include <cuda_bf16.h>
#include <math.h>
#include <float.h>

#define NB 4
#define NP 4096
#define NC 256
#define NK 16
#define NPTS (NB*NP)      /* 16384 */
#define NROWS (NPTS*NK)   /* 262144 */

// ---------------- scratch (device globals; no allocation) ----------------
__device__ float g_q [NPTS*NC];
__device__ float g_kf[NPTS*NC];
__device__ float g_vf[NPTS*NC];
__device__ int   g_idx[NROWS];
__device__ float g_u [NROWS*3];
__device__ float g_h [NROWS*NC];   // h, later reused for attn logits
__device__ float g_h2[NROWS*NC];
__device__ float g_bnd[6];         // scale[3], shift[3] for d-path BN
__device__ float g_partd[512*6];
__device__ float g_ps1[512*NC];
__device__ float g_pq1[512*NC];
__device__ float g_ps2[2048*NC];
__device__ float g_pq2[2048*NC];
__device__ float g_bn1[2*NC];
__device__ float g_bn2[2*NC];
// bf16 hi/lo split weights, [n][k] layout (n = output col, k = input channel)
__device__ __nv_bfloat16 g_bh1[NC*NC], g_bl1[NC*NC];
__device__ __nv_bfloat16 g_bh2[NC*NC], g_bl2[NC*NC];
__device__ __nv_bfloat16 g_bhq[NC*NC], g_blq[NC*NC];
__device__ __nv_bfloat16 g_bhk[NC*NC], g_blk[NC*NC];
__device__ __nv_bfloat16 g_bhv[NC*NC], g_blv[NC*NC];

// ---------------- exact-rounding helpers for KNN ----------------
__device__ __forceinline__ float sq3_exact(float x, float y, float z){
    return __fadd_rn(__fadd_rn(__fmul_rn(x,x), __fmul_rn(y,y)), __fmul_rn(z,z));
}
__device__ __forceinline__ float dist_exact(float qx,float qy,float qz,float qw,
                                            float px,float py,float pz,float pw){
    float dot = __fmaf_rn(qz, pz, __fmaf_rn(qy, py, __fmul_rn(qx, px)));
    return __fsub_rn(__fadd_rn(qw, pw), __fmul_rn(2.0f, dot));
}

// ---------------- KNN: one warp per query, chunked smem points ----------------
__global__ __launch_bounds__(512) void knn_kernel(const float* __restrict__ xyz)
{
    constexpr int CH = 2048;
    __shared__ float4 pts[CH];
    int b = blockIdx.y;
    const float* xb = xyz + b*NP*3;
    int warp = threadIdx.x >> 5, lane = threadIdx.x & 31;
    int n = blockIdx.x*16 + warp;
    float qx = xb[n*3+0], qy = xb[n*3+1], qz = xb[n*3+2];
    float qw = sq3_exact(qx, qy, qz);
    float dl[NK]; int il[NK];
#pragma unroll
    for (int j=0;j<NK;j++){ dl[j]=FLT_MAX; il[j]=0x7fffffff; }

    for (int c0=0;c0<NP;c0+=CH){
        __syncthreads();
        for (int i=threadIdx.x;i<CH;i+=512){
            int m=c0+i;
            float x=xb[m*3],y=xb[m*3+1],z=xb[m*3+2];
            pts[i]=make_float4(x,y,z, sq3_exact(x,y,z));
        }
        __syncthreads();
        for (int i=lane;i<CH;i+=32){
            float4 p=pts[i];
            int m=c0+i;
            float d = dist_exact(qx,qy,qz,qw, p.x,p.y,p.z,p.w);
            if (d < dl[NK-1] || (d==dl[NK-1] && m<il[NK-1])){
                dl[NK-1]=d; il[NK-1]=m;
#pragma unroll
                for (int j=NK-1;j>0;j--){
                    bool sw = dl[j]<dl[j-1] || (dl[j]==dl[j-1] && il[j]<il[j-1]);
                    float t0 = sw? dl[j-1]:dl[j];
                    float t1 = sw? dl[j]:dl[j-1];
                    int   i0 = sw? il[j-1]:il[j];
                    int   i1 = sw? il[j]:il[j-1];
                    dl[j]=t0; dl[j-1]=t1; il[j]=i0; il[j-1]=i1;
                }
            }
        }
    }
    for (int r=0;r<NK;r++){
        float cd = dl[0]; int ci = il[0];
        float rd = cd;    int ri = ci;
#pragma unroll
        for (int off=16; off>0; off>>=1){
            float od = __shfl_down_sync(0xffffffffu, rd, off);
            int   oi = __shfl_down_sync(0xffffffffu, ri, off);
            if (od<rd || (od==rd && oi<ri)){ rd=od; ri=oi; }
        }
        rd = __shfl_sync(0xffffffffu, rd, 0);
        ri = __shfl_sync(0xffffffffu, ri, 0);
        if (lane==0) g_idx[(b*NP+n)*NK + r] = ri;
        if (cd==rd && ci==ri){
#pragma unroll
            for (int j=0;j<NK-1;j++){ dl[j]=dl[j+1]; il[j]=il[j+1]; }
            dl[NK-1]=FLT_MAX; il[NK-1]=0x7fffffff;
        }
    }
}

// ---------------- d-path BN stats ----------------
__global__ __launch_bounds__(256) void dstat_kernel(const float* __restrict__ xyz,
                                                    const float* __restrict__ d1w,
                                                    const float* __restrict__ d1b)
{
    float s[3]={0.f,0.f,0.f}, sq[3]={0.f,0.f,0.f};
    int stride = gridDim.x*blockDim.x;
    for (int it = blockIdx.x*blockDim.x+threadIdx.x; it < NROWS; it += stride){
        int pt = it >> 4;
        int b  = pt >> 12;
        int j  = g_idx[it];
        float r0 = xyz[pt*3+0] - xyz[(b*NP+j)*3+0];
        float r1 = xyz[pt*3+1] - xyz[(b*NP+j)*3+1];
        float r2 = xyz[pt*3+2] - xyz[(b*NP+j)*3+2];
#pragma unroll
        for (int d=0;d<3;d++){
            float t = r0*d1w[d] + r1*d1w[3+d] + r2*d1w[6+d] + d1b[d];
            s[d]+=t; sq[d]+=t*t;
        }
    }
    __shared__ float red[256];
    for (int q=0;q<6;q++){
        red[threadIdx.x] = (q<3)? s[q] : sq[q-3];
        __syncthreads();
        for (int st=128; st; st>>=1){
            if (threadIdx.x<st) red[threadIdx.x]+=red[threadIdx.x+st];
            __syncthreads();
        }
        if (threadIdx.x==0) g_partd[blockIdx.x*6+q]=red[0];
        __syncthreads();
    }
}

__global__ void dfin_kernel(const float* __restrict__ g, const float* __restrict__ beta)
{
    int d = threadIdx.x;
    if (d>=3) return;
    double s=0.0,q=0.0;
    for (int i=0;i<512;i++){ s+=g_partd[i*6+d]; q+=g_partd[i*6+3+d]; }
    double m = s/(double)NROWS;
    double v = q/(double)NROWS - m*m;
    double sc = (double)g[d] / sqrt(v+1e-5);
    g_bnd[d]   = (float)sc;
    g_bnd[3+d] = (float)((double)beta[d] - m*sc);
}

// ---------------- weight prep: fp32 [k][n] -> bf16 hi/lo [n][k] ----------------
__global__ void bprep_kernel(const float* __restrict__ W,
                             __nv_bfloat16* __restrict__ H, __nv_bfloat16* __restrict__ L)
{
    int k = blockIdx.x, n = threadIdx.x;
    float w = W[k*NC+n];
    __nv_bfloat16 h = __float2bfloat16_rn(w);
    H[n*NC+k] = h;
    L[n*NC+k] = __float2bfloat16_rn(w - __bfloat162float(h));
}

// ---------------- bf16x3 tensor-core GEMM via mma.sync (HMMA, baseline sm_80+ ISA) ----
// C[M x 256] = f(A)[M x 256] @ W + bias, where W given as bf16 hi/lo [n][k].
// f = identity or BN+ReLU (scale/shift in bnp). fp32 accumulation; passes
// Ah*Bh + Ah*Bl + Al*Bh recover near-fp32 accuracy.
__device__ __forceinline__ void mma_bf16(float* c, const unsigned* a, const unsigned* b){
    asm volatile(
      "mma.sync.aligned.m16n8k16.row.col.f32.bf16.bf16.f32 "
      "{%0,%1,%2,%3}, {%4,%5,%6,%7}, {%8,%9}, {%0,%1,%2,%3};"
      : "+f"(c[0]),"+f"(c[1]),"+f"(c[2]),"+f"(c[3])
      : "r"(a[0]),"r"(a[1]),"r"(a[2]),"r"(a[3]), "r"(b[0]),"r"(b[1]));
}

#define KC 32           /* K-chunk */
#define RSTRIDE 40      /* row stride in halves: 80B = 20 words, conflict-free */

template<bool BNRELU>
__global__ __launch_bounds__(256, 2) void gemm_mma_kernel(
    const float* __restrict__ A,
    const __nv_bfloat16* __restrict__ Bh, const __nv_bfloat16* __restrict__ Bl,
    const float* __restrict__ bias, const float* __restrict__ bnp,
    float* __restrict__ C)
{
    __shared__ __align__(16) unsigned short AsH[128][RSTRIDE];
    __shared__ __align__(16) unsigned short AsL[128][RSTRIDE];
    __shared__ __align__(16) unsigned short BsH[128][RSTRIDE];
    __shared__ __align__(16) unsigned short BsL[128][RSTRIDE];

    int tid = threadIdx.x, wid = tid >> 5, lane = tid & 31;
    int g = lane >> 2, t = lane & 3;           // fragment group / thread-in-group
    int wm = wid & 3, wn = wid >> 2;           // warp tile: 32 M-rows x 64 N-cols
    const size_t rowbase = (size_t)blockIdx.x * 128;
    const int ncb = blockIdx.y * 128;

    float acc[2][8][4];
#pragma unroll
    for (int mt=0;mt<2;mt++)
#pragma unroll
        for (int nt=0;nt<8;nt++)
#pragma unroll
            for (int i=0;i<4;i++) acc[mt][nt][i]=0.f;

    int lr = tid >> 1;            // 0..127 row for staging
    int cg = (tid & 1) * 16;      // 16-element column group

    for (int kc0 = 0; kc0 < 256; kc0 += KC){
        if (kc0) __syncthreads();
        // ---- stage A: 128 x 32 fp32 -> (bnrelu) -> hi/lo bf16 ----
        {
            const float* ap = A + (rowbase + lr)*256 + kc0 + cg;
            float v[16];
            *(float4*)(v)    = *(const float4*)(ap);
            *(float4*)(v+4)  = *(const float4*)(ap+4);
            *(float4*)(v+8)  = *(const float4*)(ap+8);
            *(float4*)(v+12) = *(const float4*)(ap+12);
            unsigned hh[8], ll[8];
#pragma unroll
            for (int p=0;p<8;p++){
                float a0 = v[p*2], a1 = v[p*2+1];
                if (BNRELU){
                    int c = kc0 + cg + p*2;
                    a0 = fmaxf(0.f, fmaf(a0, bnp[c],   bnp[256+c]));
                    a1 = fmaxf(0.f, fmaf(a1, bnp[c+1], bnp[257+c]));
                }
                __nv_bfloat16 h0 = __float2bfloat16_rn(a0);
                __nv_bfloat16 h1 = __float2bfloat16_rn(a1);
                __nv_bfloat16 l0 = __float2bfloat16_rn(a0 - __bfloat162float(h0));
                __nv_bfloat16 l1 = __float2bfloat16_rn(a1 - __bfloat162float(h1));
                hh[p] = (unsigned)__bfloat16_as_ushort(h0) | ((unsigned)__bfloat16_as_ushort(h1)<<16);
                ll[p] = (unsigned)__bfloat16_as_ushort(l0) | ((unsigned)__bfloat16_as_ushort(l1)<<16);
            }
            *(uint4*)&AsH[lr][cg]   = make_uint4(hh[0],hh[1],hh[2],hh[3]);
            *(uint4*)&AsH[lr][cg+8] = make_uint4(hh[4],hh[5],hh[6],hh[7]);
            *(uint4*)&AsL[lr][cg]   = make_uint4(ll[0],ll[1],ll[2],ll[3]);
            *(uint4*)&AsL[lr][cg+8] = make_uint4(ll[4],ll[5],ll[6],ll[7]);
        }
        // ---- stage B: 128 n-rows x 32 k bf16 hi/lo ----
        {
            const __nv_bfloat16* bhp = Bh + (size_t)(ncb + lr)*256 + kc0 + cg;
            const __nv_bfloat16* blp = Bl + (size_t)(ncb + lr)*256 + kc0 + cg;
            *(uint4*)&BsH[lr][cg]   = *(const uint4*)(bhp);
            *(uint4*)&BsH[lr][cg+8] = *(const uint4*)(bhp+8);
            *(uint4*)&BsL[lr][cg]   = *(const uint4*)(blp);
            *(uint4*)&BsL[lr][cg+8] = *(const uint4*)(blp+8);
        }
        __syncthreads();

        // ---- compute: 3 passes x 2 k16-steps x (2 m-tiles x 8 n-tiles) ----
#pragma unroll
        for (int p=0;p<3;p++){
            const unsigned short (*Ap)[RSTRIDE] = (p==2)? AsL : AsH;
            const unsigned short (*Bp)[RSTRIDE] = (p==1)? BsL : BsH;
#pragma unroll
            for (int ks=0; ks<KC; ks+=16){
                unsigned af[2][4];
#pragma unroll
                for (int mt=0;mt<2;mt++){
                    int r0 = wm*32 + mt*16 + g;
                    af[mt][0] = *(const unsigned*)&Ap[r0  ][ks + 2*t];
                    af[mt][1] = *(const unsigned*)&Ap[r0+8][ks + 2*t];
                    af[mt][2] = *(const unsigned*)&Ap[r0  ][ks + 2*t + 8];
                    af[mt][3] = *(const unsigned*)&Ap[r0+8][ks + 2*t + 8];
                }
#pragma unroll
                for (int nt=0;nt<8;nt++){
                    int n0 = wn*64 + nt*8 + g;
                    unsigned bf[2];
                    bf[0] = *(const unsigned*)&Bp[n0][ks + 2*t];
                    bf[1] = *(const unsigned*)&Bp[n0][ks + 2*t + 8];
                    mma_bf16(acc[0][nt], af[0], bf);
                    mma_bf16(acc[1][nt], af[1], bf);
                }
            }
        }
    }

    // ---- epilogue: bias + store ----
#pragma unroll
    for (int nt=0;nt<8;nt++){
        int col = ncb + wn*64 + nt*8 + 2*t;
        float b0 = bias[col], b1 = bias[col+1];
#pragma unroll
        for (int mt=0;mt<2;mt++){
            size_t row = rowbase + wm*32 + mt*16 + g;
            float2 o0 = make_float2(acc[mt][nt][0] + b0, acc[mt][nt][1] + b1);
            float2 o1 = make_float2(acc[mt][nt][2] + b0, acc[mt][nt][3] + b1);
            *(float2*)&C[row*256 + col]     = o0;
            *(float2*)&C[(row+8)*256 + col] = o1;
        }
    }
}

// ---------------- streaming per-column stats (for bn2) ----------------
__global__ __launch_bounds__(256) void colstat_kernel(const float* __restrict__ X)
{
    int c = threadIdx.x;
    size_t base = (size_t)blockIdx.x * 128 * 256;
    float s = 0.f, q = 0.f;
#pragma unroll 4
    for (int r = 0; r < 128; r++){
        float v = X[base + r*256 + c];
        s += v; q += v*v;
    }
    g_ps2[blockIdx.x*NC + c] = s;
    g_pq2[blockIdx.x*NC + c] = q;
}

// ---------------- finalize per-channel BN over 256 channels ----------------
__global__ __launch_bounds__(256) void bnfin_kernel(const float* __restrict__ psum,
                                                    const float* __restrict__ psq, int P,
                                                    const float* __restrict__ g,
                                                    const float* __restrict__ beta,
                                                    float* __restrict__ outp)
{
    int c = threadIdx.x;
    double s=0.0,q=0.0;
    for (int i=0;i<P;i++){ s+=psum[i*NC+c]; q+=psq[i*NC+c]; }
    double m = s/(double)NROWS;
    double v = q/(double)NROWS - m*m;
    double sc = (double)g[c] / sqrt(v+1e-5);
    outp[c]    = (float)sc;
    outp[NC+c] = (float)((double)beta[c] - m*sc);
}

// ---------------- h producer: h = q - k[idx] + pos_enc; fused bn1 stats ----------------
__global__ __launch_bounds__(256) void hprod_kernel(
    const float* __restrict__ xyz, const float* __restrict__ d1w, const float* __restrict__ d1b,
    const float* __restrict__ d2w, const float* __restrict__ d2b)
{
    __shared__ float su[NK*3];
    __shared__ int   sj[NK];
    int c = threadIdx.x;
    float d2c0 = d2w[c], d2c1 = d2w[256+c], d2c2 = d2w[512+c], d2bc = d2b[c];
    float s=0.f, q=0.f;
    for (int pp=0; pp<32; pp++){
        int pt = blockIdx.x*32 + pp;
        int b  = pt >> 12;
        if (c < NK){
            int k = c;
            int j = g_idx[pt*NK+k];
            sj[k]=j;
            float r0 = xyz[pt*3+0]-xyz[(b*NP+j)*3+0];
            float r1 = xyz[pt*3+1]-xyz[(b*NP+j)*3+1];
            float r2 = xyz[pt*3+2]-xyz[(b*NP+j)*3+2];
#pragma unroll
            for (int d=0;d<3;d++){
                float t  = r0*d1w[d] + r1*d1w[3+d] + r2*d1w[6+d] + d1b[d];
                float uu = fmaxf(0.f, fmaf(t, g_bnd[d], g_bnd[3+d]));
                su[k*3+d]=uu;
                g_u[(pt*NK+k)*3+d]=uu;
            }
        }
        __syncthreads();
        float qv = g_q[pt*NC + c];
#pragma unroll
        for (int k=0;k<NK;k++){
            int j = sj[k];
            float kv = g_kf[(b*NP+j)*NC + c];
            float pe = su[k*3]*d2c0 + su[k*3+1]*d2c1 + su[k*3+2]*d2c2 + d2bc;
            float h = qv - kv + pe;
            g_h[(size_t)(pt*NK+k)*NC + c] = h;
            s += h; q += h*h;
        }
        __syncthreads();
    }
    g_ps1[blockIdx.x*NC+c]=s;
    g_pq1[blockIdx.x*NC+c]=q;
}

// ---------------- softmax over K + weighted gather output ----------------
__global__ __launch_bounds__(256) void out_kernel(
    float* __restrict__ out, const float* __restrict__ d2w, const float* __restrict__ d2b)
{
    __shared__ float su[NK*3];
    __shared__ int   sj[NK];
    int pt = blockIdx.x;
    int b  = pt >> 12;
    int a  = threadIdx.x;
    if (a < NK)   sj[a] = g_idx[pt*NK+a];
    if (a < NK*3) su[a] = g_u[pt*NK*3 + a];
    __syncthreads();
    float d0=d2w[a], d1=d2w[256+a], d2=d2w[512+a], db=d2b[a];
    float e[NK];
    float mx = -FLT_MAX;
#pragma unroll
    for (int k=0;k<NK;k++){
        float x = g_h[(size_t)(pt*NK+k)*NC + a];
        e[k]=x; mx = fmaxf(mx,x);
    }
    float sm=0.f;
#pragma unroll
    for (int k=0;k<NK;k++){ e[k]=expf(e[k]-mx); sm+=e[k]; }
    float inv = 1.f/sm;
    float o=0.f;
#pragma unroll
    for (int k=0;k<NK;k++){
        int j = sj[k];
        float v  = g_vf[(b*NP+j)*NC + a];
        float pe = su[k*3]*d0 + su[k*3+1]*d1 + su[k*3+2]*d2 + db;
        o += e[k]*inv*(v+pe);
    }
    out[pt*NC + a] = o;
}

// ---------------- host launcher (graph-capturable, allocation-free) ----------------
extern "C" void kernel_launch(void* const* d_in, const int* in_sizes, int n_in,
                              void* d_out, int out_size)
{
    const float* xyz  = (const float*)d_in[0];
    const float* feat = (const float*)d_in[1];
    const float* wq   = (const float*)d_in[2];  const float* bq  = (const float*)d_in[3];
    const float* wk   = (const float*)d_in[4];  const float* bk  = (const float*)d_in[5];
    const float* wv   = (const float*)d_in[6];  const float* bv  = (const float*)d_in[7];
    const float* d1w  = (const float*)d_in[8];  const float* d1b = (const float*)d_in[9];
    const float* bndg = (const float*)d_in[10]; const float* bndb= (const float*)d_in[11];
    const float* d2w  = (const float*)d_in[12]; const float* d2b = (const float*)d_in[13];
    const float* g1g  = (const float*)d_in[14]; const float* g1bt= (const float*)d_in[15];
    const float* g1w  = (const float*)d_in[16]; const float* g1b = (const float*)d_in[17];
    const float* g2g  = (const float*)d_in[18]; const float* g2bt= (const float*)d_in[19];
    const float* g2w  = (const float*)d_in[20]; const float* g2b = (const float*)d_in[21];
    float* out = (float*)d_out;

    float *p_q,*p_kf,*p_vf,*p_h,*p_h2,*p_bn1,*p_bn2,*p_ps1,*p_pq1,*p_ps2,*p_pq2;
    __nv_bfloat16 *p_bh1,*p_bl1,*p_bh2,*p_bl2,*p_bhq,*p_blq,*p_bhk,*p_blk,*p_bhv,*p_blv;
    cudaGetSymbolAddress((void**)&p_q,  g_q);
    cudaGetSymbolAddress((void**)&p_kf, g_kf);
    cudaGetSymbolAddress((void**)&p_vf, g_vf);
    cudaGetSymbolAddress((void**)&p_h,  g_h);
    cudaGetSymbolAddress((void**)&p_h2, g_h2);
    cudaGetSymbolAddress((void**)&p_bn1,g_bn1);
    cudaGetSymbolAddress((void**)&p_bn2,g_bn2);
    cudaGetSymbolAddress((void**)&p_ps1,g_ps1);
    cudaGetSymbolAddress((void**)&p_pq1,g_pq1);
    cudaGetSymbolAddress((void**)&p_ps2,g_ps2);
    cudaGetSymbolAddress((void**)&p_pq2,g_pq2);
    cudaGetSymbolAddress((void**)&p_bh1,g_bh1);
    cudaGetSymbolAddress((void**)&p_bl1,g_bl1);
    cudaGetSymbolAddress((void**)&p_bh2,g_bh2);
    cudaGetSymbolAddress((void**)&p_bl2,g_bl2);
    cudaGetSymbolAddress((void**)&p_bhq,g_bhq);
    cudaGetSymbolAddress((void**)&p_blq,g_blq);
    cudaGetSymbolAddress((void**)&p_bhk,g_bhk);
    cudaGetSymbolAddress((void**)&p_blk,g_blk);
    cudaGetSymbolAddress((void**)&p_bhv,g_bhv);
    cudaGetSymbolAddress((void**)&p_blv,g_blv);

    // 1. KNN indices
    knn_kernel<<<dim3(NP/16, NB), 512>>>(xyz);
    // 2. d-path BN stats + finalize; weight splits
    dstat_kernel<<<512,256>>>(xyz, d1w, d1b);
    dfin_kernel<<<1,32>>>(bndg, bndb);
    bprep_kernel<<<NC,NC>>>(g1w, p_bh1, p_bl1);
    bprep_kernel<<<NC,NC>>>(g2w, p_bh2, p_bl2);
    bprep_kernel<<<NC,NC>>>(wq,  p_bhq, p_blq);
    bprep_kernel<<<NC,NC>>>(wk,  p_bhk, p_blk);
    bprep_kernel<<<NC,NC>>>(wv,  p_bhv, p_blv);
    // 3. q / k / v projections (HMMA bf16x3)
    gemm_mma_kernel<false><<<dim3(NPTS/128,2),256>>>(feat, p_bhq, p_blq, bq, nullptr, p_q);
    gemm_mma_kernel<false><<<dim3(NPTS/128,2),256>>>(feat, p_bhk, p_blk, bk, nullptr, p_kf);
    gemm_mma_kernel<false><<<dim3(NPTS/128,2),256>>>(feat, p_bhv, p_blv, bv, nullptr, p_vf);
    // 4. h = q - k[idx] + pos_enc (stores u, fused bn1 stats)
    hprod_kernel<<<512,256>>>(xyz, d1w, d1b, d2w, d2b);
    bnfin_kernel<<<1,256>>>(p_ps1, p_pq1, 512, g1g, g1bt, p_bn1);
    // 5. gamma layer 1 (HMMA): relu(bn1(h)) @ g1_w + g1_b -> h2
    gemm_mma_kernel<true><<<dim3(NROWS/128,2),256>>>(p_h, p_bh1, p_bl1, g1b, p_bn1, p_h2);
    // 6. bn2 stats from h2
    colstat_kernel<<<2048,256>>>(p_h2);
    bnfin_kernel<<<1,256>>>(p_ps2, p_pq2, 2048, g2g, g2bt, p_bn2);
    // 7. gamma layer 2 (HMMA): relu(bn2(h2)) @ g2_w + g2_b -> attn logits
    gemm_mma_kernel<true><<<dim3(NROWS/128,2),256>>>(p_h2, p_bh2, p_bl2, g2b, p_bn2, p_h);
    // 8. softmax over K + weighted (v + pos_enc) sum
    out_kernel<<<NPTS,256>>>(out, d2w, d2b);
}